// round 14
// baseline (speedup 1.0000x reference)
#include <cuda_runtime.h>
#include <cuda_bf16.h>
#include <math.h>
#include <stdint.h>

#define H 16
#define S 2048
#define D 128
#define M 4096
#define TOPK 16
#define QT 128            // queries per CTA
#define CK 64             // keys per chunk
#define NCH (M / CK)      // 64 chunks
#define NKEEP 18          // per-lane candidates per (row, key-quarter)
#define NCAND 72          // per-query candidates (4 quarters x 18)

// Scratch (device globals; cudaMalloc is forbidden)
__device__ __align__(16) float          g_kn [H * M * D];
__device__ __align__(16) float          g_qn [H * S * D];
__device__ __align__(16) __nv_bfloat16  g_knb[H * M * D];
__device__ __align__(16) __nv_bfloat16  g_qnb[H * S * D];
__device__ __align__(16) uint16_t       g_cand[H * S * NCAND];   // 4.7 MB

// ---------------- K1 smem layout (bytes) ----------------
#define LDT 136                    // bf16 row stride (128 + 8 pad) = 272 B
#define SM_A   0                   // A tile 128 x 272B = 34816
#define SM_B0  34816               // key buf 0: 64 x 272B = 17408
#define SM_B1  52224               // key buf 1: 17408
#define SM_TOTAL 69632

// ---------------- K2 smem layout (bytes, dynamic) ----------------
#define K2_CI  0                   // u16 [128][72] = 18432
#define K2_CS  18432               // f32 [128][73] = 37376
#define K2_FS  55808               // f32 [128][16] = 8192
#define K2_FI  64000               // u16 [128][16] = 4096
#define K2_TOTAL 68096

__device__ __forceinline__ uint32_t smem_u32(const void* p) {
    uint32_t a;
    asm("{ .reg .u64 t; cvta.to.shared.u64 t, %1; cvt.u32.u64 %0, t; }" : "=r"(a) : "l"(p));
    return a;
}
#define CP_ASYNC16(dst, src) \
    asm volatile("cp.async.cg.shared.global [%0], [%1], 16;" :: "r"(dst), "l"(src))
#define CP_COMMIT() asm volatile("cp.async.commit_group;" ::: "memory")
#define CP_WAIT(n)  asm volatile("cp.async.wait_group %0;" :: "n"(n) : "memory")

#define LDMATRIX_X4(r0, r1, r2, r3, a) \
    asm volatile("ldmatrix.sync.aligned.m8n8.x4.shared.b16 {%0,%1,%2,%3}, [%4];" \
                 : "=r"(r0), "=r"(r1), "=r"(r2), "=r"(r3) : "r"(a))

#define MMA16816(c0, c1, c2, c3, a0, a1, a2, a3, b0, b1) \
    asm volatile("mma.sync.aligned.m16n8k16.row.col.f32.bf16.bf16.f32 " \
                 "{%0,%1,%2,%3}, {%4,%5,%6,%7}, {%8,%9}, {%0,%1,%2,%3};" \
                 : "+f"(c0), "+f"(c1), "+f"(c2), "+f"(c3) \
                 : "r"(a0), "r"(a1), "r"(a2), "r"(a3), "r"(b0), "r"(b1))

// Running top-NKEEP of packed (order-preserving score hi-bits | 12-bit idx).
// Cheap conservative prefilter on the high 20 bits, exact test inside.
__device__ __forceinline__ void updTop(uint32_t (&ls)[NKEEP], uint32_t& lmin,
                                       float s, uint32_t idx) {
    uint32_t b = __float_as_uint(s);
    b = ((int)b < 0) ? ~b : (b | 0x80000000u);
    b &= 0xFFFFF000u;
    if (b >= (lmin & 0xFFFFF000u)) {
        uint32_t u = b | idx;
        if (u > lmin) {
            bool done = false;
#pragma unroll
            for (int j = 0; j < NKEEP; j++)
                if (!done && ls[j] == lmin) { ls[j] = u; done = true; }
            lmin = ls[0];
#pragma unroll
            for (int j = 1; j < NKEEP; j++) lmin = min(lmin, ls[j]);
        }
    }
}

// ---------------------------------------------------------------------------
// Exact row L2-normalization (XLA:CPU rounding: sequential mul/add, no FMA)
// emits fp32 + bf16 copies. Blocks [0, kblocks) -> kmem, rest -> query.
// ---------------------------------------------------------------------------
__global__ __launch_bounds__(256)
void normalize_rows2(const float* __restrict__ kmem, const float* __restrict__ query,
                     float* __restrict__ kn, float* __restrict__ qn,
                     __nv_bfloat16* __restrict__ knb, __nv_bfloat16* __restrict__ qnb,
                     int kblocks) {
    __shared__ float rows[64 * 129];
    __shared__ float rnorm[64];
    const int tid = threadIdx.x;
    const float* src; float* dst; __nv_bfloat16* dstb; size_t base;
    if ((int)blockIdx.x < kblocks) {
        src = kmem; dst = kn; dstb = knb; base = (size_t)blockIdx.x * 64 * D;
    } else {
        src = query; dst = qn; dstb = qnb; base = (size_t)(blockIdx.x - kblocks) * 64 * D;
    }
#pragma unroll
    for (int i = 0; i < 32; i++) {
        int idx = i * 256 + tid; int r = idx >> 7; int d = idx & 127;
        rows[r * 129 + d] = src[base + (size_t)r * D + d];
    }
    __syncthreads();
    if (tid < 64) {
        const float* rp = rows + tid * 129;
        float acc = 0.f;
#pragma unroll 8
        for (int d = 0; d < D; d++) acc = __fadd_rn(acc, __fmul_rn(rp[d], rp[d]));
        rnorm[tid] = fmaxf(__fsqrt_rn(acc), 1e-6f);
    }
    __syncthreads();
#pragma unroll
    for (int i = 0; i < 32; i++) {
        int idx = i * 256 + tid; int r = idx >> 7; int d = idx & 127;
        float v = __fdiv_rn(rows[r * 129 + d], rnorm[r]);
        dst[base + (size_t)r * D + d]  = v;
        dstb[base + (size_t)r * D + d] = __float2bfloat16(v);
    }
}

// ---------------------------------------------------------------------------
// K1: bf16 mma.sync sims; top-k directly on MMA fragments.
// kk-outer / p-inner: A fragments loaded ONCE per kk (8 A-LDSM per chunk
// instead of 32); all 32 accumulators live across the kk loop.
// Lane (g = lane>>2, t = lane&3) owns rows {g, g+8} and key-quarter t.
// Two top-18 packed lists per lane -> 72 candidates/query, dumped to global.
// ---------------------------------------------------------------------------
__global__ __launch_bounds__(256, 2)
void k1_sims(void) {
    extern __shared__ char sm[];
    const uint32_t sb = smem_u32(sm);

    const int tid  = threadIdx.x;
    const int wid  = tid >> 5;
    const int lane = tid & 31;
    const int h     = blockIdx.y;
    const int qtile = blockIdx.x;
    const int qbase = qtile * QT;
    const int g     = lane >> 2;
    const int t     = lane & 3;

    // stage A (query tile) bf16 into smem
    {
        const __nv_bfloat16* qb = g_qnb + ((size_t)h * S + qbase) * D;
#pragma unroll
        for (int i = 0; i < 8; i++) {
            int idx = i * 256 + tid;
            int row = idx >> 4, g16 = idx & 15;
            uint4 v = *reinterpret_cast<const uint4*>(qb + (size_t)row * D + g16 * 8);
            *reinterpret_cast<uint4*>(sm + SM_A + row * (LDT * 2) + g16 * 16) = v;
        }
    }

    const __nv_bfloat16* kb = g_knb + (size_t)h * M * D;
    auto load_chunk = [&](int c) {
        const __nv_bfloat16* kc = kb + (size_t)c * CK * D;
        uint32_t bs = sb + ((c & 1) ? SM_B1 : SM_B0);
#pragma unroll
        for (int i = 0; i < 4; i++) {
            int idx = i * 256 + tid;
            int row = idx >> 4, g16 = idx & 15;
            CP_ASYNC16(bs + row * (LDT * 2) + g16 * 16,
                       kc + (size_t)row * D + g16 * 8);
        }
    };
    load_chunk(0); CP_COMMIT();

    // per-lane ldmatrix bases
    const int rA = wid * 16 + (lane & 7) + ((lane >> 3) & 1) * 8;
    const uint32_t baseA = sb + SM_A + rA * (LDT * 2) + ((lane >> 4) & 1) * 16;
    uint32_t baseB[4];
#pragma unroll
    for (int p = 0; p < 4; p++) {
        int key = p * 16 + ((lane >> 4) & 1) * 8 + (lane & 7);
        baseB[p] = key * (LDT * 2) + ((lane >> 3) & 1) * 16;
    }

    uint32_t lsA[NKEEP], lsB[NKEEP];
    uint32_t lminA = 0, lminB = 0;
#pragma unroll
    for (int j = 0; j < NKEEP; j++) { lsA[j] = 0; lsB[j] = 0; }

    for (int c = 0; c < NCH; c++) {
        if (c < NCH - 1) { load_chunk(c + 1); CP_COMMIT(); CP_WAIT(1); }
        else             { CP_WAIT(0); }
        __syncthreads();

        const uint32_t bbuf = sb + ((c & 1) ? SM_B1 : SM_B0);
        float acc[4][8];          // [p][c0..c7]
#pragma unroll
        for (int p = 0; p < 4; p++)
#pragma unroll
            for (int j = 0; j < 8; j++) acc[p][j] = 0.f;

#pragma unroll
        for (int kk = 0; kk < 8; kk++) {
            uint32_t a0, a1, a2, a3;
            LDMATRIX_X4(a0, a1, a2, a3, baseA + kk * 32);
#pragma unroll
            for (int p = 0; p < 4; p++) {
                uint32_t b0, b1, b2, b3;
                LDMATRIX_X4(b0, b1, b2, b3, bbuf + baseB[p] + kk * 32);
                MMA16816(acc[p][0], acc[p][1], acc[p][2], acc[p][3],
                         a0, a1, a2, a3, b0, b1);
                MMA16816(acc[p][4], acc[p][5], acc[p][6], acc[p][7],
                         a0, a1, a2, a3, b2, b3);
            }
        }

#pragma unroll
        for (int p = 0; p < 4; p++) {
            const uint32_t kbase = (uint32_t)(c * CK + p * 16);
            // row g (lists A): keys kbase+2t, +1, kbase+8+2t, +1
            updTop(lsA, lminA, acc[p][0], kbase + 2 * t);
            updTop(lsA, lminA, acc[p][1], kbase + 2 * t + 1);
            updTop(lsA, lminA, acc[p][4], kbase + 8 + 2 * t);
            updTop(lsA, lminA, acc[p][5], kbase + 8 + 2 * t + 1);
            // row g+8 (lists B)
            updTop(lsB, lminB, acc[p][2], kbase + 2 * t);
            updTop(lsB, lminB, acc[p][3], kbase + 2 * t + 1);
            updTop(lsB, lminB, acc[p][6], kbase + 8 + 2 * t);
            updTop(lsB, lminB, acc[p][7], kbase + 8 + 2 * t + 1);
        }
        __syncthreads();   // retire B reads before next chunk's cp.async
    }

    // dump candidate indices: 18 per (row, quarter)
    {
        int qA = qbase + wid * 16 + g;
        int qB = qA + 8;
        uint16_t* dA = g_cand + ((size_t)h * S + qA) * NCAND + t * NKEEP;
        uint16_t* dB = g_cand + ((size_t)h * S + qB) * NCAND + t * NKEEP;
#pragma unroll
        for (int j = 0; j < NKEEP; j++) {
            dA[j] = (uint16_t)(lsA[j] & 0xFFFu);
            dB[j] = (uint16_t)(lsB[j] & 0xFFFu);
        }
    }
}

// ---------------------------------------------------------------------------
// K2: exact epilogue. Rescore 72 candidates/query with the bit-exact
// sequential fp32 FMA chain, exact merge (desc, lowest-index ties),
// descending weighted gather, gated combine.
// ---------------------------------------------------------------------------
__global__ __launch_bounds__(256, 2)
void k2_exact(const float* __restrict__ outputs, const float* __restrict__ gate,
              const float* __restrict__ vmem, float* __restrict__ out) {
    extern __shared__ char sm2[];
    uint16_t* sCI = (uint16_t*)(sm2 + K2_CI);
    float*    sCS = (float*)(sm2 + K2_CS);
    float*    sFS = (float*)(sm2 + K2_FS);
    uint16_t* sFI = (uint16_t*)(sm2 + K2_FI);

    const int tid   = threadIdx.x;
    const int h     = blockIdx.y;
    const int qtile = blockIdx.x;
    const int qbase = qtile * QT;

    // load candidate indices (128*72 u16 = 1152 uint4)
    {
        const uint4* src = reinterpret_cast<const uint4*>(
            g_cand + ((size_t)h * S + qbase) * NCAND);
#pragma unroll
        for (int i = 0; i < 5; i++) {
            int idx = i * 256 + tid;
            if (idx < QT * NCAND / 8)
                reinterpret_cast<uint4*>(sCI)[idx] = src[idx];
        }
    }
    __syncthreads();

    // exact fp32 rescore: sequential FMA chain over d=0..127
    {
        const int qq = tid >> 1;
        const int j0 = (tid & 1) * 36;
        const float4* qrow = reinterpret_cast<const float4*>(
            g_qn + ((size_t)h * S + qbase + qq) * D);
        const float* knh = g_kn + (size_t)h * M * D;
#pragma unroll
        for (int grp = 0; grp < 9; grp++) {
            const float4* kr[4];
#pragma unroll
            for (int i = 0; i < 4; i++) {
                int ki = (int)sCI[qq * NCAND + j0 + grp * 4 + i];
                kr[i] = reinterpret_cast<const float4*>(knh + (size_t)ki * D);
            }
            float a0 = 0.f, a1 = 0.f, a2 = 0.f, a3 = 0.f;
#pragma unroll 4
            for (int v = 0; v < 32; v++) {
                float4 qv = qrow[v];
                float4 k0 = kr[0][v], k1 = kr[1][v], k2 = kr[2][v], k3 = kr[3][v];
                a0 = __fmaf_rn(qv.x, k0.x, a0); a0 = __fmaf_rn(qv.y, k0.y, a0);
                a0 = __fmaf_rn(qv.z, k0.z, a0); a0 = __fmaf_rn(qv.w, k0.w, a0);
                a1 = __fmaf_rn(qv.x, k1.x, a1); a1 = __fmaf_rn(qv.y, k1.y, a1);
                a1 = __fmaf_rn(qv.z, k1.z, a1); a1 = __fmaf_rn(qv.w, k1.w, a1);
                a2 = __fmaf_rn(qv.x, k2.x, a2); a2 = __fmaf_rn(qv.y, k2.y, a2);
                a2 = __fmaf_rn(qv.z, k2.z, a2); a2 = __fmaf_rn(qv.w, k2.w, a2);
                a3 = __fmaf_rn(qv.x, k3.x, a3); a3 = __fmaf_rn(qv.y, k3.y, a3);
                a3 = __fmaf_rn(qv.z, k3.z, a3); a3 = __fmaf_rn(qv.w, k3.w, a3);
            }
            sCS[qq * 73 + j0 + grp * 4 + 0] = a0;
            sCS[qq * 73 + j0 + grp * 4 + 1] = a1;
            sCS[qq * 73 + j0 + grp * 4 + 2] = a2;
            sCS[qq * 73 + j0 + grp * 4 + 3] = a3;
        }
    }
    __syncthreads();

    // exact merge: top-16 of 72, descending, lowest-index tie-break
    if (tid < QT) {
        int qq = tid;
        for (int p = 0; p < TOPK; p++) {
            float best = -INFINITY; int bj = 0; int bi = 0x7fffffff;
            for (int j = 0; j < NCAND; j++) {
                float v = sCS[qq * 73 + j];
                int idx = (int)sCI[qq * NCAND + j];
                if (v > best || (v == best && idx < bi)) { best = v; bj = j; bi = idx; }
            }
            sFS[qq * TOPK + p] = best;
            sFI[qq * TOPK + p] = (uint16_t)bi;
            sCS[qq * 73 + bj] = -INFINITY;
        }
    }
    __syncthreads();

    // weighted value gather (descending) + gated combine
    {
        const int oq = tid >> 1;
        const int dh = tid & 1;
        float4 a4[16];
#pragma unroll
        for (int j = 0; j < 16; j++) a4[j] = make_float4(0.f, 0.f, 0.f, 0.f);
        const float4* vm4 = reinterpret_cast<const float4*>(vmem + (size_t)h * M * D);
        for (int n = 0; n < TOPK; n++) {
            float w  = sFS[oq * TOPK + n];
            int   ki = (int)sFI[oq * TOPK + n];
            const float4* row = vm4 + (size_t)ki * (D / 4) + dh * 16;
#pragma unroll
            for (int j = 0; j < 16; j++) {
                float4 v = row[j];
                a4[j].x = __fmaf_rn(w, v.x, a4[j].x);
                a4[j].y = __fmaf_rn(w, v.y, a4[j].y);
                a4[j].z = __fmaf_rn(w, v.z, a4[j].z);
                a4[j].w = __fmaf_rn(w, v.w, a4[j].w);
            }
        }
        float gv = gate[h];
        float gg = __fdiv_rn(1.f, __fadd_rn(1.f, expf(-gv)));
        float og = __fsub_rn(1.f, gg);
        size_t ob = (((size_t)h * S + qbase + oq) * D) + (size_t)dh * 64;
        const float4* o4 = reinterpret_cast<const float4*>(outputs + ob);
        float4*       w4 = reinterpret_cast<float4*>(out + ob);
#pragma unroll
        for (int j = 0; j < 16; j++) {
            float4 o = o4[j];
            float4 r;
            r.x = __fadd_rn(__fmul_rn(gg, a4[j].x), __fmul_rn(og, o.x));
            r.y = __fadd_rn(__fmul_rn(gg, a4[j].y), __fmul_rn(og, o.y));
            r.z = __fadd_rn(__fmul_rn(gg, a4[j].z), __fmul_rn(og, o.z));
            r.w = __fadd_rn(__fmul_rn(gg, a4[j].w), __fmul_rn(og, o.w));
            w4[j] = r;
        }
    }
}

// ---------------------------------------------------------------------------
// inputs: 0 inputs, 1 query, 2 key, 3 value, 4 outputs, 5 gate,
//         6 key_memories, 7 value_memories
// ---------------------------------------------------------------------------
extern "C" void kernel_launch(void* const* d_in, const int* in_sizes, int n_in,
                              void* d_out, int out_size) {
    (void)in_sizes; (void)n_in; (void)out_size;
    const float* query   = (const float*)d_in[1];
    const float* outputs = (const float*)d_in[4];
    const float* gate    = (const float*)d_in[5];
    const float* kmem    = (const float*)d_in[6];
    const float* vmem    = (const float*)d_in[7];
    float* out = (float*)d_out;

    float *kn_p, *qn_p; __nv_bfloat16 *knb_p, *qnb_p;
    cudaGetSymbolAddress((void**)&kn_p, g_kn);
    cudaGetSymbolAddress((void**)&qn_p, g_qn);
    cudaGetSymbolAddress((void**)&knb_p, g_knb);
    cudaGetSymbolAddress((void**)&qnb_p, g_qnb);

    const int kblocks = (H * M) / 64;   // 1024
    const int qblocks = (H * S) / 64;   // 512
    normalize_rows2<<<kblocks + qblocks, 256>>>(kmem, query, kn_p, qn_p, knb_p, qnb_p, kblocks);

    static int configured = 0;
    if (!configured) {
        cudaFuncSetAttribute(k1_sims, cudaFuncAttributeMaxDynamicSharedMemorySize, SM_TOTAL);
        cudaFuncSetAttribute(k2_exact, cudaFuncAttributeMaxDynamicSharedMemorySize, K2_TOTAL);
        configured = 1;
    }
    dim3 grid(S / QT, H);   // 16 x 16 = 256 CTAs
    k1_sims<<<grid, 256, SM_TOTAL>>>();
    k2_exact<<<grid, 256, K2_TOTAL>>>(outputs, gate, vmem, out);
}

// round 15
// speedup vs baseline: 1.0003x; 1.0003x over previous
#include <cuda_runtime.h>
#include <cuda_bf16.h>
#include <math.h>
#include <stdint.h>

#define H 16
#define S 2048
#define D 128
#define M 4096
#define TOPK 16
#define QT 128            // queries per CTA
#define CK 64             // keys per chunk
#define NCH (M / CK)      // 64 chunks
#define NKEEP 18          // per-lane candidates per (row, key-quarter)
#define NCAND 72          // per-query candidates (4 quarters x 18)

// Scratch (device globals; cudaMalloc is forbidden)
__device__ __align__(16) float          g_kn [H * M * D];
__device__ __align__(16) float          g_qn [H * S * D];
__device__ __align__(16) __nv_bfloat16  g_knb[H * M * D];
__device__ __align__(16) __nv_bfloat16  g_qnb[H * S * D];
__device__ __align__(16) uint16_t       g_cand[H * S * NCAND];   // 4.7 MB

// ---------------- K1 smem layout (bytes) ----------------
#define LDT 136                    // bf16 row stride (128 + 8 pad) = 272 B
#define SM_A   0                   // A tile 128 x 272B = 34816
#define SM_B0  34816               // key buf 0: 64 x 272B = 17408
#define SM_B1  52224               // key buf 1: 17408
#define SM_TOTAL 69632

// ---------------- K2 smem layout (bytes, dynamic) ----------------
#define K2_CI  0                   // u16 [128][72] = 18432
#define K2_CS  18432               // f32 [128][73] = 37376
#define K2_FS  55808               // f32 [128][16] = 8192
#define K2_FI  64000               // u16 [128][16] = 4096
#define K2_TOTAL 68096

__device__ __forceinline__ uint32_t smem_u32(const void* p) {
    uint32_t a;
    asm("{ .reg .u64 t; cvta.to.shared.u64 t, %1; cvt.u32.u64 %0, t; }" : "=r"(a) : "l"(p));
    return a;
}
#define CP_ASYNC16(dst, src) \
    asm volatile("cp.async.cg.shared.global [%0], [%1], 16;" :: "r"(dst), "l"(src))
#define CP_COMMIT() asm volatile("cp.async.commit_group;" ::: "memory")
#define CP_WAIT(n)  asm volatile("cp.async.wait_group %0;" :: "n"(n) : "memory")

#define LDMATRIX_X4(r0, r1, r2, r3, a) \
    asm volatile("ldmatrix.sync.aligned.m8n8.x4.shared.b16 {%0,%1,%2,%3}, [%4];" \
                 : "=r"(r0), "=r"(r1), "=r"(r2), "=r"(r3) : "r"(a))

#define MMA16816(c0, c1, c2, c3, a0, a1, a2, a3, b0, b1) \
    asm volatile("mma.sync.aligned.m16n8k16.row.col.f32.bf16.bf16.f32 " \
                 "{%0,%1,%2,%3}, {%4,%5,%6,%7}, {%8,%9}, {%0,%1,%2,%3};" \
                 : "+f"(c0), "+f"(c1), "+f"(c2), "+f"(c3) \
                 : "r"(a0), "r"(a1), "r"(a2), "r"(a3), "r"(b0), "r"(b1))

// Running top-NKEEP of packed (order-preserving score hi-bits | 12-bit idx).
// Cheap conservative prefilter on the high 20 bits, exact test inside.
__device__ __forceinline__ void updTop(uint32_t (&ls)[NKEEP], uint32_t& lmin,
                                       float s, uint32_t idx) {
    uint32_t b = __float_as_uint(s);
    b = ((int)b < 0) ? ~b : (b | 0x80000000u);
    b &= 0xFFFFF000u;
    if (b >= (lmin & 0xFFFFF000u)) {
        uint32_t u = b | idx;
        if (u > lmin) {
            bool done = false;
#pragma unroll
            for (int j = 0; j < NKEEP; j++)
                if (!done && ls[j] == lmin) { ls[j] = u; done = true; }
            lmin = ls[0];
#pragma unroll
            for (int j = 1; j < NKEEP; j++) lmin = min(lmin, ls[j]);
        }
    }
}

// ---------------------------------------------------------------------------
// Exact row L2-normalization (XLA:CPU rounding: sequential mul/add, no FMA)
// emits fp32 + bf16 copies. Blocks [0, kblocks) -> kmem, rest -> query.
// ---------------------------------------------------------------------------
__global__ __launch_bounds__(256)
void normalize_rows2(const float* __restrict__ kmem, const float* __restrict__ query,
                     float* __restrict__ kn, float* __restrict__ qn,
                     __nv_bfloat16* __restrict__ knb, __nv_bfloat16* __restrict__ qnb,
                     int kblocks) {
    __shared__ float rows[64 * 129];
    __shared__ float rnorm[64];
    const int tid = threadIdx.x;
    const float* src; float* dst; __nv_bfloat16* dstb; size_t base;
    if ((int)blockIdx.x < kblocks) {
        src = kmem; dst = kn; dstb = knb; base = (size_t)blockIdx.x * 64 * D;
    } else {
        src = query; dst = qn; dstb = qnb; base = (size_t)(blockIdx.x - kblocks) * 64 * D;
    }
#pragma unroll
    for (int i = 0; i < 32; i++) {
        int idx = i * 256 + tid; int r = idx >> 7; int d = idx & 127;
        rows[r * 129 + d] = src[base + (size_t)r * D + d];
    }
    __syncthreads();
    if (tid < 64) {
        const float* rp = rows + tid * 129;
        float acc = 0.f;
#pragma unroll 8
        for (int d = 0; d < D; d++) acc = __fadd_rn(acc, __fmul_rn(rp[d], rp[d]));
        rnorm[tid] = fmaxf(__fsqrt_rn(acc), 1e-6f);
    }
    __syncthreads();
#pragma unroll
    for (int i = 0; i < 32; i++) {
        int idx = i * 256 + tid; int r = idx >> 7; int d = idx & 127;
        float v = __fdiv_rn(rows[r * 129 + d], rnorm[r]);
        dst[base + (size_t)r * D + d]  = v;
        dstb[base + (size_t)r * D + d] = __float2bfloat16(v);
    }
}

// ---------------------------------------------------------------------------
// K1: bf16 mma.sync sims; top-k directly on MMA fragments.
// kk-outer / p-inner: A fragments loaded ONCE per kk (8 A-LDSM per chunk
// instead of 32); all 32 accumulators live across the kk loop.
// Lane (g = lane>>2, t = lane&3) owns rows {g, g+8} and key-quarter t.
// Two top-18 packed lists per lane -> 72 candidates/query, dumped to global.
// ---------------------------------------------------------------------------
__global__ __launch_bounds__(256, 2)
void k1_sims(void) {
    extern __shared__ char sm[];
    const uint32_t sb = smem_u32(sm);

    const int tid  = threadIdx.x;
    const int wid  = tid >> 5;
    const int lane = tid & 31;
    const int h     = blockIdx.y;
    const int qtile = blockIdx.x;
    const int qbase = qtile * QT;
    const int g     = lane >> 2;
    const int t     = lane & 3;

    // stage A (query tile) bf16 into smem
    {
        const __nv_bfloat16* qb = g_qnb + ((size_t)h * S + qbase) * D;
#pragma unroll
        for (int i = 0; i < 8; i++) {
            int idx = i * 256 + tid;
            int row = idx >> 4, g16 = idx & 15;
            uint4 v = *reinterpret_cast<const uint4*>(qb + (size_t)row * D + g16 * 8);
            *reinterpret_cast<uint4*>(sm + SM_A + row * (LDT * 2) + g16 * 16) = v;
        }
    }

    const __nv_bfloat16* kb = g_knb + (size_t)h * M * D;
    auto load_chunk = [&](int c) {
        const __nv_bfloat16* kc = kb + (size_t)c * CK * D;
        uint32_t bs = sb + ((c & 1) ? SM_B1 : SM_B0);
#pragma unroll
        for (int i = 0; i < 4; i++) {
            int idx = i * 256 + tid;
            int row = idx >> 4, g16 = idx & 15;
            CP_ASYNC16(bs + row * (LDT * 2) + g16 * 16,
                       kc + (size_t)row * D + g16 * 8);
        }
    };
    load_chunk(0); CP_COMMIT();

    // per-lane ldmatrix bases
    const int rA = wid * 16 + (lane & 7) + ((lane >> 3) & 1) * 8;
    const uint32_t baseA = sb + SM_A + rA * (LDT * 2) + ((lane >> 4) & 1) * 16;
    uint32_t baseB[4];
#pragma unroll
    for (int p = 0; p < 4; p++) {
        int key = p * 16 + ((lane >> 4) & 1) * 8 + (lane & 7);
        baseB[p] = key * (LDT * 2) + ((lane >> 3) & 1) * 16;
    }

    uint32_t lsA[NKEEP], lsB[NKEEP];
    uint32_t lminA = 0, lminB = 0;
#pragma unroll
    for (int j = 0; j < NKEEP; j++) { lsA[j] = 0; lsB[j] = 0; }

    for (int c = 0; c < NCH; c++) {
        if (c < NCH - 1) { load_chunk(c + 1); CP_COMMIT(); CP_WAIT(1); }
        else             { CP_WAIT(0); }
        __syncthreads();

        const uint32_t bbuf = sb + ((c & 1) ? SM_B1 : SM_B0);
        float acc[4][8];          // [p][c0..c7]
#pragma unroll
        for (int p = 0; p < 4; p++)
#pragma unroll
            for (int j = 0; j < 8; j++) acc[p][j] = 0.f;

#pragma unroll
        for (int kk = 0; kk < 8; kk++) {
            uint32_t a0, a1, a2, a3;
            LDMATRIX_X4(a0, a1, a2, a3, baseA + kk * 32);
#pragma unroll
            for (int p = 0; p < 4; p++) {
                uint32_t b0, b1, b2, b3;
                LDMATRIX_X4(b0, b1, b2, b3, bbuf + baseB[p] + kk * 32);
                MMA16816(acc[p][0], acc[p][1], acc[p][2], acc[p][3],
                         a0, a1, a2, a3, b0, b1);
                MMA16816(acc[p][4], acc[p][5], acc[p][6], acc[p][7],
                         a0, a1, a2, a3, b2, b3);
            }
        }

#pragma unroll
        for (int p = 0; p < 4; p++) {
            const uint32_t kbase = (uint32_t)(c * CK + p * 16);
            // row g (lists A): keys kbase+2t, +1, kbase+8+2t, +1
            updTop(lsA, lminA, acc[p][0], kbase + 2 * t);
            updTop(lsA, lminA, acc[p][1], kbase + 2 * t + 1);
            updTop(lsA, lminA, acc[p][4], kbase + 8 + 2 * t);
            updTop(lsA, lminA, acc[p][5], kbase + 8 + 2 * t + 1);
            // row g+8 (lists B)
            updTop(lsB, lminB, acc[p][2], kbase + 2 * t);
            updTop(lsB, lminB, acc[p][3], kbase + 2 * t + 1);
            updTop(lsB, lminB, acc[p][6], kbase + 8 + 2 * t);
            updTop(lsB, lminB, acc[p][7], kbase + 8 + 2 * t + 1);
        }
        __syncthreads();   // retire B reads before next chunk's cp.async
    }

    // dump candidate indices: 18 per (row, quarter)
    {
        int qA = qbase + wid * 16 + g;
        int qB = qA + 8;
        uint16_t* dA = g_cand + ((size_t)h * S + qA) * NCAND + t * NKEEP;
        uint16_t* dB = g_cand + ((size_t)h * S + qB) * NCAND + t * NKEEP;
#pragma unroll
        for (int j = 0; j < NKEEP; j++) {
            dA[j] = (uint16_t)(lsA[j] & 0xFFFu);
            dB[j] = (uint16_t)(lsB[j] & 0xFFFu);
        }
    }
}

// ---------------------------------------------------------------------------
// K2: exact epilogue. Rescore 72 candidates/query with the bit-exact
// sequential fp32 FMA chain, exact merge (desc, lowest-index ties),
// descending weighted gather, gated combine.
// ---------------------------------------------------------------------------
__global__ __launch_bounds__(256, 2)
void k2_exact(const float* __restrict__ outputs, const float* __restrict__ gate,
              const float* __restrict__ vmem, float* __restrict__ out) {
    extern __shared__ char sm2[];
    uint16_t* sCI = (uint16_t*)(sm2 + K2_CI);
    float*    sCS = (float*)(sm2 + K2_CS);
    float*    sFS = (float*)(sm2 + K2_FS);
    uint16_t* sFI = (uint16_t*)(sm2 + K2_FI);

    const int tid   = threadIdx.x;
    const int h     = blockIdx.y;
    const int qtile = blockIdx.x;
    const int qbase = qtile * QT;

    // load candidate indices (128*72 u16 = 1152 uint4)
    {
        const uint4* src = reinterpret_cast<const uint4*>(
            g_cand + ((size_t)h * S + qbase) * NCAND);
#pragma unroll
        for (int i = 0; i < 5; i++) {
            int idx = i * 256 + tid;
            if (idx < QT * NCAND / 8)
                reinterpret_cast<uint4*>(sCI)[idx] = src[idx];
        }
    }
    __syncthreads();

    // exact fp32 rescore: sequential FMA chain over d=0..127
    {
        const int qq = tid >> 1;
        const int j0 = (tid & 1) * 36;
        const float4* qrow = reinterpret_cast<const float4*>(
            g_qn + ((size_t)h * S + qbase + qq) * D);
        const float* knh = g_kn + (size_t)h * M * D;
#pragma unroll
        for (int grp = 0; grp < 9; grp++) {
            const float4* kr[4];
#pragma unroll
            for (int i = 0; i < 4; i++) {
                int ki = (int)sCI[qq * NCAND + j0 + grp * 4 + i];
                kr[i] = reinterpret_cast<const float4*>(knh + (size_t)ki * D);
            }
            float a0 = 0.f, a1 = 0.f, a2 = 0.f, a3 = 0.f;
#pragma unroll 4
            for (int v = 0; v < 32; v++) {
                float4 qv = qrow[v];
                float4 k0 = kr[0][v], k1 = kr[1][v], k2 = kr[2][v], k3 = kr[3][v];
                a0 = __fmaf_rn(qv.x, k0.x, a0); a0 = __fmaf_rn(qv.y, k0.y, a0);
                a0 = __fmaf_rn(qv.z, k0.z, a0); a0 = __fmaf_rn(qv.w, k0.w, a0);
                a1 = __fmaf_rn(qv.x, k1.x, a1); a1 = __fmaf_rn(qv.y, k1.y, a1);
                a1 = __fmaf_rn(qv.z, k1.z, a1); a1 = __fmaf_rn(qv.w, k1.w, a1);
                a2 = __fmaf_rn(qv.x, k2.x, a2); a2 = __fmaf_rn(qv.y, k2.y, a2);
                a2 = __fmaf_rn(qv.z, k2.z, a2); a2 = __fmaf_rn(qv.w, k2.w, a2);
                a3 = __fmaf_rn(qv.x, k3.x, a3); a3 = __fmaf_rn(qv.y, k3.y, a3);
                a3 = __fmaf_rn(qv.z, k3.z, a3); a3 = __fmaf_rn(qv.w, k3.w, a3);
            }
            sCS[qq * 73 + j0 + grp * 4 + 0] = a0;
            sCS[qq * 73 + j0 + grp * 4 + 1] = a1;
            sCS[qq * 73 + j0 + grp * 4 + 2] = a2;
            sCS[qq * 73 + j0 + grp * 4 + 3] = a3;
        }
    }
    __syncthreads();

    // exact merge: top-16 of 72, descending, lowest-index tie-break
    if (tid < QT) {
        int qq = tid;
        for (int p = 0; p < TOPK; p++) {
            float best = -INFINITY; int bj = 0; int bi = 0x7fffffff;
            for (int j = 0; j < NCAND; j++) {
                float v = sCS[qq * 73 + j];
                int idx = (int)sCI[qq * NCAND + j];
                if (v > best || (v == best && idx < bi)) { best = v; bj = j; bi = idx; }
            }
            sFS[qq * TOPK + p] = best;
            sFI[qq * TOPK + p] = (uint16_t)bi;
            sCS[qq * 73 + bj] = -INFINITY;
        }
    }
    __syncthreads();

    // weighted value gather (descending) + gated combine
    {
        const int oq = tid >> 1;
        const int dh = tid & 1;
        float4 a4[16];
#pragma unroll
        for (int j = 0; j < 16; j++) a4[j] = make_float4(0.f, 0.f, 0.f, 0.f);
        const float4* vm4 = reinterpret_cast<const float4*>(vmem + (size_t)h * M * D);
        for (int n = 0; n < TOPK; n++) {
            float w  = sFS[oq * TOPK + n];
            int   ki = (int)sFI[oq * TOPK + n];
            const float4* row = vm4 + (size_t)ki * (D / 4) + dh * 16;
#pragma unroll
            for (int j = 0; j < 16; j++) {
                float4 v = row[j];
                a4[j].x = __fmaf_rn(w, v.x, a4[j].x);
                a4[j].y = __fmaf_rn(w, v.y, a4[j].y);
                a4[j].z = __fmaf_rn(w, v.z, a4[j].z);
                a4[j].w = __fmaf_rn(w, v.w, a4[j].w);
            }
        }
        float gv = gate[h];
        float gg = __fdiv_rn(1.f, __fadd_rn(1.f, expf(-gv)));
        float og = __fsub_rn(1.f, gg);
        size_t ob = (((size_t)h * S + qbase + oq) * D) + (size_t)dh * 64;
        const float4* o4 = reinterpret_cast<const float4*>(outputs + ob);
        float4*       w4 = reinterpret_cast<float4*>(out + ob);
#pragma unroll
        for (int j = 0; j < 16; j++) {
            float4 o = o4[j];
            float4 r;
            r.x = __fadd_rn(__fmul_rn(gg, a4[j].x), __fmul_rn(og, o.x));
            r.y = __fadd_rn(__fmul_rn(gg, a4[j].y), __fmul_rn(og, o.y));
            r.z = __fadd_rn(__fmul_rn(gg, a4[j].z), __fmul_rn(og, o.z));
            r.w = __fadd_rn(__fmul_rn(gg, a4[j].w), __fmul_rn(og, o.w));
            w4[j] = r;
        }
    }
}

// ---------------------------------------------------------------------------
// inputs: 0 inputs, 1 query, 2 key, 3 value, 4 outputs, 5 gate,
//         6 key_memories, 7 value_memories
// ---------------------------------------------------------------------------
extern "C" void kernel_launch(void* const* d_in, const int* in_sizes, int n_in,
                              void* d_out, int out_size) {
    (void)in_sizes; (void)n_in; (void)out_size;
    const float* query   = (const float*)d_in[1];
    const float* outputs = (const float*)d_in[4];
    const float* gate    = (const float*)d_in[5];
    const float* kmem    = (const float*)d_in[6];
    const float* vmem    = (const float*)d_in[7];
    float* out = (float*)d_out;

    float *kn_p, *qn_p; __nv_bfloat16 *knb_p, *qnb_p;
    cudaGetSymbolAddress((void**)&kn_p, g_kn);
    cudaGetSymbolAddress((void**)&qn_p, g_qn);
    cudaGetSymbolAddress((void**)&knb_p, g_knb);
    cudaGetSymbolAddress((void**)&qnb_p, g_qnb);

    const int kblocks = (H * M) / 64;   // 1024
    const int qblocks = (H * S) / 64;   // 512
    normalize_rows2<<<kblocks + qblocks, 256>>>(kmem, query, kn_p, qn_p, knb_p, qnb_p, kblocks);

    static int configured = 0;
    if (!configured) {
        cudaFuncSetAttribute(k1_sims, cudaFuncAttributeMaxDynamicSharedMemorySize, SM_TOTAL);
        cudaFuncSetAttribute(k2_exact, cudaFuncAttributeMaxDynamicSharedMemorySize, K2_TOTAL);
        configured = 1;
    }
    dim3 grid(S / QT, H);   // 16 x 16 = 256 CTAs
    k1_sims<<<grid, 256, SM_TOTAL>>>();
    k2_exact<<<grid, 256, K2_TOTAL>>>(outputs, gate, vmem, out);
}

// round 16
// speedup vs baseline: 1.0167x; 1.0163x over previous
#include <cuda_runtime.h>
#include <cuda_bf16.h>
#include <math.h>
#include <stdint.h>

#define H 16
#define S 2048
#define D 128
#define M 4096
#define TOPK 16
#define QT 128            // queries per CTA
#define CK 64             // keys per chunk
#define NCH (M / CK)      // 64 chunks
#define NKEEP 18          // per-lane candidates per (row, key-quarter)
#define NCAND 72          // per-query candidates (4 quarters x 18)

// Scratch (device globals; cudaMalloc is forbidden)
__device__ __align__(16) float          g_kn [H * M * D];
__device__ __align__(16) float          g_qn [H * S * D];
__device__ __align__(16) __nv_bfloat16  g_knb[H * M * D];
__device__ __align__(16) __nv_bfloat16  g_qnb[H * S * D];
__device__ __align__(16) uint16_t       g_cand[H * S * NCAND];   // 4.7 MB

// ---------------- K1 smem layout (bytes) ----------------
#define LDT 136                    // bf16 row stride (128 + 8 pad) = 272 B
#define SM_A   0                   // A tile 128 x 272B = 34816
#define SM_B0  34816               // key buf 0: 64 x 272B = 17408
#define SM_B1  52224               // key buf 1: 17408
#define SM_TOTAL 69632

// ---------------- K2 smem layout (bytes, dynamic) ----------------
#define K2_CI  0                   // u16 [128][72] = 18432
#define K2_CS  18432               // f32 [128][73] = 37376
#define K2_FS  55808               // f32 [128][16] = 8192
#define K2_FI  64000               // u16 [128][16] = 4096
#define K2_TOTAL 68096

__device__ __forceinline__ uint32_t smem_u32(const void* p) {
    uint32_t a;
    asm("{ .reg .u64 t; cvta.to.shared.u64 t, %1; cvt.u32.u64 %0, t; }" : "=r"(a) : "l"(p));
    return a;
}
#define CP_ASYNC16(dst, src) \
    asm volatile("cp.async.cg.shared.global [%0], [%1], 16;" :: "r"(dst), "l"(src))
#define CP_COMMIT() asm volatile("cp.async.commit_group;" ::: "memory")
#define CP_WAIT(n)  asm volatile("cp.async.wait_group %0;" :: "n"(n) : "memory")

#define LDMATRIX_X4(r0, r1, r2, r3, a) \
    asm volatile("ldmatrix.sync.aligned.m8n8.x4.shared.b16 {%0,%1,%2,%3}, [%4];" \
                 : "=r"(r0), "=r"(r1), "=r"(r2), "=r"(r3) : "r"(a))

#define MMA16816(c0, c1, c2, c3, a0, a1, a2, a3, b0, b1) \
    asm volatile("mma.sync.aligned.m16n8k16.row.col.f32.bf16.bf16.f32 " \
                 "{%0,%1,%2,%3}, {%4,%5,%6,%7}, {%8,%9}, {%0,%1,%2,%3};" \
                 : "+f"(c0), "+f"(c1), "+f"(c2), "+f"(c3) \
                 : "r"(a0), "r"(a1), "r"(a2), "r"(a3), "r"(b0), "r"(b1))

// Running top-NKEEP of packed (order-preserving score hi-bits | 12-bit idx).
// Cheap conservative prefilter on the high 20 bits, exact test inside.
__device__ __forceinline__ void updTop(uint32_t (&ls)[NKEEP], uint32_t& lmin,
                                       float s, uint32_t idx) {
    uint32_t b = __float_as_uint(s);
    b = ((int)b < 0) ? ~b : (b | 0x80000000u);
    b &= 0xFFFFF000u;
    if (b >= (lmin & 0xFFFFF000u)) {
        uint32_t u = b | idx;
        if (u > lmin) {
            bool done = false;
#pragma unroll
            for (int j = 0; j < NKEEP; j++)
                if (!done && ls[j] == lmin) { ls[j] = u; done = true; }
            lmin = ls[0];
#pragma unroll
            for (int j = 1; j < NKEEP; j++) lmin = min(lmin, ls[j]);
        }
    }
}

// ---------------------------------------------------------------------------
// Exact row L2-normalization (XLA:CPU rounding: sequential mul/add, no FMA)
// emits fp32 + bf16 copies. Blocks [0, kblocks) -> kmem, rest -> query.
// ---------------------------------------------------------------------------
__global__ __launch_bounds__(256)
void normalize_rows2(const float* __restrict__ kmem, const float* __restrict__ query,
                     float* __restrict__ kn, float* __restrict__ qn,
                     __nv_bfloat16* __restrict__ knb, __nv_bfloat16* __restrict__ qnb,
                     int kblocks) {
    __shared__ float rows[64 * 129];
    __shared__ float rnorm[64];
    const int tid = threadIdx.x;
    const float* src; float* dst; __nv_bfloat16* dstb; size_t base;
    if ((int)blockIdx.x < kblocks) {
        src = kmem; dst = kn; dstb = knb; base = (size_t)blockIdx.x * 64 * D;
    } else {
        src = query; dst = qn; dstb = qnb; base = (size_t)(blockIdx.x - kblocks) * 64 * D;
    }
#pragma unroll
    for (int i = 0; i < 32; i++) {
        int idx = i * 256 + tid; int r = idx >> 7; int d = idx & 127;
        rows[r * 129 + d] = src[base + (size_t)r * D + d];
    }
    __syncthreads();
    if (tid < 64) {
        const float* rp = rows + tid * 129;
        float acc = 0.f;
#pragma unroll 8
        for (int d = 0; d < D; d++) acc = __fadd_rn(acc, __fmul_rn(rp[d], rp[d]));
        rnorm[tid] = fmaxf(__fsqrt_rn(acc), 1e-6f);
    }
    __syncthreads();
#pragma unroll
    for (int i = 0; i < 32; i++) {
        int idx = i * 256 + tid; int r = idx >> 7; int d = idx & 127;
        float v = __fdiv_rn(rows[r * 129 + d], rnorm[r]);
        dst[base + (size_t)r * D + d]  = v;
        dstb[base + (size_t)r * D + d] = __float2bfloat16(v);
    }
}

// ---------------------------------------------------------------------------
// K1: bf16 mma.sync sims; top-k directly on MMA fragments.
// kk-outer / p-inner: A fragments loaded ONCE per kk (8 A-LDSM per chunk
// instead of 32); all 32 accumulators live across the kk loop.
// Lane (g = lane>>2, t = lane&3) owns rows {g, g+8} and key-quarter t.
// Two top-18 packed lists per lane -> 72 candidates/query, dumped to global.
// ---------------------------------------------------------------------------
__global__ __launch_bounds__(256, 2)
void k1_sims(void) {
    extern __shared__ char sm[];
    const uint32_t sb = smem_u32(sm);

    const int tid  = threadIdx.x;
    const int wid  = tid >> 5;
    const int lane = tid & 31;
    const int h     = blockIdx.y;
    const int qtile = blockIdx.x;
    const int qbase = qtile * QT;
    const int g     = lane >> 2;
    const int t     = lane & 3;

    // stage A (query tile) bf16 into smem
    {
        const __nv_bfloat16* qb = g_qnb + ((size_t)h * S + qbase) * D;
#pragma unroll
        for (int i = 0; i < 8; i++) {
            int idx = i * 256 + tid;
            int row = idx >> 4, g16 = idx & 15;
            uint4 v = *reinterpret_cast<const uint4*>(qb + (size_t)row * D + g16 * 8);
            *reinterpret_cast<uint4*>(sm + SM_A + row * (LDT * 2) + g16 * 16) = v;
        }
    }

    const __nv_bfloat16* kb = g_knb + (size_t)h * M * D;
    auto load_chunk = [&](int c) {
        const __nv_bfloat16* kc = kb + (size_t)c * CK * D;
        uint32_t bs = sb + ((c & 1) ? SM_B1 : SM_B0);
#pragma unroll
        for (int i = 0; i < 4; i++) {
            int idx = i * 256 + tid;
            int row = idx >> 4, g16 = idx & 15;
            CP_ASYNC16(bs + row * (LDT * 2) + g16 * 16,
                       kc + (size_t)row * D + g16 * 8);
        }
    };
    load_chunk(0); CP_COMMIT();

    // per-lane ldmatrix bases
    const int rA = wid * 16 + (lane & 7) + ((lane >> 3) & 1) * 8;
    const uint32_t baseA = sb + SM_A + rA * (LDT * 2) + ((lane >> 4) & 1) * 16;
    uint32_t baseB[4];
#pragma unroll
    for (int p = 0; p < 4; p++) {
        int key = p * 16 + ((lane >> 4) & 1) * 8 + (lane & 7);
        baseB[p] = key * (LDT * 2) + ((lane >> 3) & 1) * 16;
    }

    uint32_t lsA[NKEEP], lsB[NKEEP];
    uint32_t lminA = 0, lminB = 0;
#pragma unroll
    for (int j = 0; j < NKEEP; j++) { lsA[j] = 0; lsB[j] = 0; }

    for (int c = 0; c < NCH; c++) {
        if (c < NCH - 1) { load_chunk(c + 1); CP_COMMIT(); CP_WAIT(1); }
        else             { CP_WAIT(0); }
        __syncthreads();

        const uint32_t bbuf = sb + ((c & 1) ? SM_B1 : SM_B0);
        float acc[4][8];          // [p][c0..c7]
#pragma unroll
        for (int p = 0; p < 4; p++)
#pragma unroll
            for (int j = 0; j < 8; j++) acc[p][j] = 0.f;

#pragma unroll
        for (int kk = 0; kk < 8; kk++) {
            uint32_t a0, a1, a2, a3;
            LDMATRIX_X4(a0, a1, a2, a3, baseA + kk * 32);
#pragma unroll
            for (int p = 0; p < 4; p++) {
                uint32_t b0, b1, b2, b3;
                LDMATRIX_X4(b0, b1, b2, b3, bbuf + baseB[p] + kk * 32);
                MMA16816(acc[p][0], acc[p][1], acc[p][2], acc[p][3],
                         a0, a1, a2, a3, b0, b1);
                MMA16816(acc[p][4], acc[p][5], acc[p][6], acc[p][7],
                         a0, a1, a2, a3, b2, b3);
            }
        }

#pragma unroll
        for (int p = 0; p < 4; p++) {
            const uint32_t kbase = (uint32_t)(c * CK + p * 16);
            // row g (lists A): keys kbase+2t, +1, kbase+8+2t, +1
            updTop(lsA, lminA, acc[p][0], kbase + 2 * t);
            updTop(lsA, lminA, acc[p][1], kbase + 2 * t + 1);
            updTop(lsA, lminA, acc[p][4], kbase + 8 + 2 * t);
            updTop(lsA, lminA, acc[p][5], kbase + 8 + 2 * t + 1);
            // row g+8 (lists B)
            updTop(lsB, lminB, acc[p][2], kbase + 2 * t);
            updTop(lsB, lminB, acc[p][3], kbase + 2 * t + 1);
            updTop(lsB, lminB, acc[p][6], kbase + 8 + 2 * t);
            updTop(lsB, lminB, acc[p][7], kbase + 8 + 2 * t + 1);
        }
        __syncthreads();   // retire B reads before next chunk's cp.async
    }

    // dump candidate indices: 18 per (row, quarter)
    {
        int qA = qbase + wid * 16 + g;
        int qB = qA + 8;
        uint16_t* dA = g_cand + ((size_t)h * S + qA) * NCAND + t * NKEEP;
        uint16_t* dB = g_cand + ((size_t)h * S + qB) * NCAND + t * NKEEP;
#pragma unroll
        for (int j = 0; j < NKEEP; j++) {
            dA[j] = (uint16_t)(lsA[j] & 0xFFFu);
            dB[j] = (uint16_t)(lsB[j] & 0xFFFu);
        }
    }
}

// ---------------------------------------------------------------------------
// K2: exact epilogue. Rescore 72 candidates/query with the bit-exact
// sequential fp32 FMA chain, exact merge (desc, lowest-index ties),
// descending weighted gather, gated combine.
// ---------------------------------------------------------------------------
__global__ __launch_bounds__(256, 2)
void k2_exact(const float* __restrict__ outputs, const float* __restrict__ gate,
              const float* __restrict__ vmem, float* __restrict__ out) {
    extern __shared__ char sm2[];
    uint16_t* sCI = (uint16_t*)(sm2 + K2_CI);
    float*    sCS = (float*)(sm2 + K2_CS);
    float*    sFS = (float*)(sm2 + K2_FS);
    uint16_t* sFI = (uint16_t*)(sm2 + K2_FI);

    const int tid   = threadIdx.x;
    const int h     = blockIdx.y;
    const int qtile = blockIdx.x;
    const int qbase = qtile * QT;

    // load candidate indices (128*72 u16 = 1152 uint4)
    {
        const uint4* src = reinterpret_cast<const uint4*>(
            g_cand + ((size_t)h * S + qbase) * NCAND);
#pragma unroll
        for (int i = 0; i < 5; i++) {
            int idx = i * 256 + tid;
            if (idx < QT * NCAND / 8)
                reinterpret_cast<uint4*>(sCI)[idx] = src[idx];
        }
    }
    __syncthreads();

    // exact fp32 rescore: sequential FMA chain over d=0..127
    {
        const int qq = tid >> 1;
        const int j0 = (tid & 1) * 36;
        const float4* qrow = reinterpret_cast<const float4*>(
            g_qn + ((size_t)h * S + qbase + qq) * D);
        const float* knh = g_kn + (size_t)h * M * D;
#pragma unroll
        for (int grp = 0; grp < 9; grp++) {
            const float4* kr[4];
#pragma unroll
            for (int i = 0; i < 4; i++) {
                int ki = (int)sCI[qq * NCAND + j0 + grp * 4 + i];
                kr[i] = reinterpret_cast<const float4*>(knh + (size_t)ki * D);
            }
            float a0 = 0.f, a1 = 0.f, a2 = 0.f, a3 = 0.f;
#pragma unroll 4
            for (int v = 0; v < 32; v++) {
                float4 qv = qrow[v];
                float4 k0 = kr[0][v], k1 = kr[1][v], k2 = kr[2][v], k3 = kr[3][v];
                a0 = __fmaf_rn(qv.x, k0.x, a0); a0 = __fmaf_rn(qv.y, k0.y, a0);
                a0 = __fmaf_rn(qv.z, k0.z, a0); a0 = __fmaf_rn(qv.w, k0.w, a0);
                a1 = __fmaf_rn(qv.x, k1.x, a1); a1 = __fmaf_rn(qv.y, k1.y, a1);
                a1 = __fmaf_rn(qv.z, k1.z, a1); a1 = __fmaf_rn(qv.w, k1.w, a1);
                a2 = __fmaf_rn(qv.x, k2.x, a2); a2 = __fmaf_rn(qv.y, k2.y, a2);
                a2 = __fmaf_rn(qv.z, k2.z, a2); a2 = __fmaf_rn(qv.w, k2.w, a2);
                a3 = __fmaf_rn(qv.x, k3.x, a3); a3 = __fmaf_rn(qv.y, k3.y, a3);
                a3 = __fmaf_rn(qv.z, k3.z, a3); a3 = __fmaf_rn(qv.w, k3.w, a3);
            }
            sCS[qq * 73 + j0 + grp * 4 + 0] = a0;
            sCS[qq * 73 + j0 + grp * 4 + 1] = a1;
            sCS[qq * 73 + j0 + grp * 4 + 2] = a2;
            sCS[qq * 73 + j0 + grp * 4 + 3] = a3;
        }
    }
    __syncthreads();

    // exact merge: top-16 of 72, descending, lowest-index tie-break
    if (tid < QT) {
        int qq = tid;
        for (int p = 0; p < TOPK; p++) {
            float best = -INFINITY; int bj = 0; int bi = 0x7fffffff;
            for (int j = 0; j < NCAND; j++) {
                float v = sCS[qq * 73 + j];
                int idx = (int)sCI[qq * NCAND + j];
                if (v > best || (v == best && idx < bi)) { best = v; bj = j; bi = idx; }
            }
            sFS[qq * TOPK + p] = best;
            sFI[qq * TOPK + p] = (uint16_t)bi;
            sCS[qq * 73 + bj] = -INFINITY;
        }
    }
    __syncthreads();

    // weighted value gather (descending) + gated combine
    {
        const int oq = tid >> 1;
        const int dh = tid & 1;
        float4 a4[16];
#pragma unroll
        for (int j = 0; j < 16; j++) a4[j] = make_float4(0.f, 0.f, 0.f, 0.f);
        const float4* vm4 = reinterpret_cast<const float4*>(vmem + (size_t)h * M * D);
        for (int n = 0; n < TOPK; n++) {
            float w  = sFS[oq * TOPK + n];
            int   ki = (int)sFI[oq * TOPK + n];
            const float4* row = vm4 + (size_t)ki * (D / 4) + dh * 16;
#pragma unroll
            for (int j = 0; j < 16; j++) {
                float4 v = row[j];
                a4[j].x = __fmaf_rn(w, v.x, a4[j].x);
                a4[j].y = __fmaf_rn(w, v.y, a4[j].y);
                a4[j].z = __fmaf_rn(w, v.z, a4[j].z);
                a4[j].w = __fmaf_rn(w, v.w, a4[j].w);
            }
        }
        float gv = gate[h];
        float gg = __fdiv_rn(1.f, __fadd_rn(1.f, expf(-gv)));
        float og = __fsub_rn(1.f, gg);
        size_t ob = (((size_t)h * S + qbase + oq) * D) + (size_t)dh * 64;
        const float4* o4 = reinterpret_cast<const float4*>(outputs + ob);
        float4*       w4 = reinterpret_cast<float4*>(out + ob);
#pragma unroll
        for (int j = 0; j < 16; j++) {
            float4 o = o4[j];
            float4 r;
            r.x = __fadd_rn(__fmul_rn(gg, a4[j].x), __fmul_rn(og, o.x));
            r.y = __fadd_rn(__fmul_rn(gg, a4[j].y), __fmul_rn(og, o.y));
            r.z = __fadd_rn(__fmul_rn(gg, a4[j].z), __fmul_rn(og, o.z));
            r.w = __fadd_rn(__fmul_rn(gg, a4[j].w), __fmul_rn(og, o.w));
            w4[j] = r;
        }
    }
}

// ---------------------------------------------------------------------------
// inputs: 0 inputs, 1 query, 2 key, 3 value, 4 outputs, 5 gate,
//         6 key_memories, 7 value_memories
// ---------------------------------------------------------------------------
extern "C" void kernel_launch(void* const* d_in, const int* in_sizes, int n_in,
                              void* d_out, int out_size) {
    (void)in_sizes; (void)n_in; (void)out_size;
    const float* query   = (const float*)d_in[1];
    const float* outputs = (const float*)d_in[4];
    const float* gate    = (const float*)d_in[5];
    const float* kmem    = (const float*)d_in[6];
    const float* vmem    = (const float*)d_in[7];
    float* out = (float*)d_out;

    float *kn_p, *qn_p; __nv_bfloat16 *knb_p, *qnb_p;
    cudaGetSymbolAddress((void**)&kn_p, g_kn);
    cudaGetSymbolAddress((void**)&qn_p, g_qn);
    cudaGetSymbolAddress((void**)&knb_p, g_knb);
    cudaGetSymbolAddress((void**)&qnb_p, g_qnb);

    const int kblocks = (H * M) / 64;   // 1024
    const int qblocks = (H * S) / 64;   // 512
    normalize_rows2<<<kblocks + qblocks, 256>>>(kmem, query, kn_p, qn_p, knb_p, qnb_p, kblocks);

    static int configured = 0;
    if (!configured) {
        cudaFuncSetAttribute(k1_sims, cudaFuncAttributeMaxDynamicSharedMemorySize, SM_TOTAL);
        cudaFuncSetAttribute(k2_exact, cudaFuncAttributeMaxDynamicSharedMemorySize, K2_TOTAL);
        configured = 1;
    }
    dim3 grid(S / QT, H);   // 16 x 16 = 256 CTAs
    k1_sims<<<grid, 256, SM_TOTAL>>>();
    k2_exact<<<grid, 256, K2_TOTAL>>>(outputs, gate, vmem, out);
}